// round 5
// baseline (speedup 1.0000x reference)
#include <cuda_runtime.h>
#include <math.h>

// Problem constants
#define BATCH 4
#define SEQ   2048
#define CDIM  1024
#define NH    16
#define HD    64
#define ROWS  (BATCH*SEQ)      // 8192
#define QKVC  (3*CDIM)         // 3072

// Scratch (allocation-free rule: __device__ globals)
__device__ float g_qkv[(size_t)ROWS * QKVC];  // [B*T, 3C]  q|k|v
__device__ float g_y[(size_t)ROWS * CDIM];    // attention output [B,T,C]

__device__ __forceinline__ unsigned f2tf32(float f) {
    unsigned r;
    asm("cvt.rna.tf32.f32 %0, %1;" : "=r"(r) : "f"(f));
    return r;
}

__device__ __forceinline__ void mma_tf32(float c[4], unsigned a0, unsigned a1,
                                         unsigned a2, unsigned a3,
                                         unsigned b0, unsigned b1) {
    asm volatile(
        "mma.sync.aligned.m16n8k8.row.col.f32.tf32.tf32.f32 "
        "{%0,%1,%2,%3}, {%4,%5,%6,%7}, {%8,%9}, {%0,%1,%2,%3};\n"
        : "+f"(c[0]), "+f"(c[1]), "+f"(c[2]), "+f"(c[3])
        : "r"(a0), "r"(a1), "r"(a2), "r"(a3), "r"(b0), "r"(b1));
}

// ---------------------------------------------------------------------------
// tf32 tensor-core GEMM + bias, fragment-major smem layout.
// C[M,N] = A[M,K] @ B[K,N] + bias[N]
// Block 128x128x16, 256 thr = 8 warps (2x4), warp 64x32, thread 4x4 mma tiles.
// Loaders fetch raw fp32 per-fragment, convert tf32 once, STS vectorized;
// mainloop fragments are single LDS.128 (A) / LDS.64 (B), conflict-free.
// Requires M%128==0, N%128==0, K%16==0.
// ---------------------------------------------------------------------------
__global__ __launch_bounds__(256)
void gemm_tf32(const float* __restrict__ A, const float* __restrict__ B,
               const float* __restrict__ bias, float* __restrict__ C,
               int M, int N, int K)
{
    // [stage][kb][warpM][mt][lane][reg]
    __shared__ unsigned As[2][2][2][4][32][4];   // 16 KB
    // [stage][kb][warpN][nt][lane][reg]
    __shared__ unsigned Bs[2][2][4][4][32][2];   // 16 KB

    const int tid   = threadIdx.x;
    const int wid   = tid >> 5;
    const int lane  = tid & 31;
    const int warpM = wid >> 2;          // 0..1
    const int warpN = wid & 3;           // 0..3
    const int group = lane >> 2;         // 0..7
    const int tig   = lane & 3;          // 0..3

    const int rowBase = blockIdx.y * 128;
    const int colBase = blockIdx.x * 128;

    // A loader mapping: thread -> (warpM_l, mt_l, lane_l); 2 kb slots each
    const int aWm = tid >> 7;
    const int aMt = (tid >> 5) & 3;
    const int aL  = tid & 31;
    const int aG  = aL >> 2;
    const int aT  = aL & 3;
    const int aR  = rowBase + aWm * 64 + aMt * 16 + aG;   // rows aR, aR+8

    // B loader mapping: 4 slots s = tid + 256*i
    int bKb[4], bWn[4], bNt[4], bL[4];
#pragma unroll
    for (int i = 0; i < 4; i++) {
        int s = tid + 256 * i;
        bKb[i] = s >> 9; bWn[i] = (s >> 7) & 3; bNt[i] = (s >> 5) & 3; bL[i] = s & 31;
    }

    float a_st[2][4];
    float b_st[4][2];

    auto ldTile = [&](int k0) {
#pragma unroll
        for (int kb = 0; kb < 2; kb++) {
            const float* p = A + (size_t)aR * K + k0 + kb * 8 + aT;
            a_st[kb][0] = p[0];
            a_st[kb][1] = p[(size_t)8 * K];
            a_st[kb][2] = p[4];
            a_st[kb][3] = p[(size_t)8 * K + 4];
        }
#pragma unroll
        for (int i = 0; i < 4; i++) {
            // k row = k0 + kb*8 + tig   (R3 BUG: k0 was missing here)
            const float* p = B + (size_t)(k0 + bKb[i] * 8 + (bL[i] & 3)) * N
                               + colBase + bWn[i] * 32 + bNt[i] * 8 + (bL[i] >> 2);
            b_st[i][0] = p[0];
            b_st[i][1] = p[(size_t)4 * N];
        }
    };

    auto stTile = [&](int st) {
#pragma unroll
        for (int kb = 0; kb < 2; kb++) {
            uint4 v = make_uint4(f2tf32(a_st[kb][0]), f2tf32(a_st[kb][1]),
                                 f2tf32(a_st[kb][2]), f2tf32(a_st[kb][3]));
            *(uint4*)&As[st][kb][aWm][aMt][aL][0] = v;
        }
#pragma unroll
        for (int i = 0; i < 4; i++) {
            uint2 v = make_uint2(f2tf32(b_st[i][0]), f2tf32(b_st[i][1]));
            *(uint2*)&Bs[st][bKb[i]][bWn[i]][bNt[i]][bL[i]][0] = v;
        }
    };

    float acc[4][4][4];
#pragma unroll
    for (int mt = 0; mt < 4; mt++)
#pragma unroll
        for (int nt = 0; nt < 4; nt++)
#pragma unroll
            for (int i = 0; i < 4; i++) acc[mt][nt][i] = 0.f;

    const int nTiles = K >> 4;

    ldTile(0);
    for (int kt = 0; kt < nTiles; kt++) {
        const int st = kt & 1;
        stTile(st);
        __syncthreads();
        if (kt + 1 < nTiles) ldTile((kt + 1) << 4);

#pragma unroll
        for (int kb = 0; kb < 2; kb++) {
            unsigned af[4][4];
#pragma unroll
            for (int mt = 0; mt < 4; mt++)
                *(uint4*)af[mt] = *(const uint4*)&As[st][kb][warpM][mt][lane][0];
            unsigned bf[4][2];
#pragma unroll
            for (int nt = 0; nt < 4; nt++)
                *(uint2*)bf[nt] = *(const uint2*)&Bs[st][kb][warpN][nt][lane][0];
#pragma unroll
            for (int mt = 0; mt < 4; mt++)
#pragma unroll
                for (int nt = 0; nt < 4; nt++)
                    mma_tf32(acc[mt][nt], af[mt][0], af[mt][1], af[mt][2],
                             af[mt][3], bf[nt][0], bf[nt][1]);
        }
        __syncthreads();
    }

    // epilogue: C = acc + bias
#pragma unroll
    for (int mt = 0; mt < 4; mt++) {
        int r0 = rowBase + warpM * 64 + mt * 16 + group;
#pragma unroll
        for (int nt = 0; nt < 4; nt++) {
            int c = colBase + warpN * 32 + nt * 8 + 2 * tig;
            float b0 = bias[c], b1 = bias[c + 1];
            float2 v0 = make_float2(acc[mt][nt][0] + b0, acc[mt][nt][1] + b1);
            float2 v1 = make_float2(acc[mt][nt][2] + b0, acc[mt][nt][3] + b1);
            *(float2*)&C[(size_t)(r0 + 0) * N + c] = v0;
            *(float2*)&C[(size_t)(r0 + 8) * N + c] = v1;
        }
    }
}

// ---------------------------------------------------------------------------
// Tensor-core flash attention (unchanged from R2).
// ---------------------------------------------------------------------------
#define BQ 128
#define BKV 64
#define KS_STRIDE 68
#define VS_STRIDE 72
#define PS_STRIDE 68
#define ATTN_SMEM ((BKV*KS_STRIDE + BKV*VS_STRIDE + BQ*PS_STRIDE) * 4)

__global__ __launch_bounds__(256)
void attn_tc(const float* __restrict__ qkv, float* __restrict__ y)
{
    extern __shared__ unsigned smem[];
    unsigned* Ks = smem;
    unsigned* Vs = Ks + BKV * KS_STRIDE;
    unsigned* Ps = Vs + BKV * VS_STRIDE;

    const int q0 = blockIdx.x * BQ;
    const int h  = blockIdx.y;
    const int b  = blockIdx.z;

    const int tid  = threadIdx.x;
    const int w    = tid >> 5;
    const int lane = tid & 31;
    const int g    = lane >> 2;
    const int t    = lane & 3;

    const size_t base = (size_t)b * SEQ * QKVC;
    const int hoff = h * HD;
    const int rowA = q0 + w * 16 + g;

    unsigned qa[8][4];
    {
        const float* Q0 = qkv + base + (size_t)rowA * QKVC + hoff;
        const float* Q8 = Q0 + (size_t)8 * QKVC;
#pragma unroll
        for (int kb = 0; kb < 8; kb++) {
            qa[kb][0] = f2tf32(Q0[kb * 8 + t] * 0.125f);
            qa[kb][1] = f2tf32(Q8[kb * 8 + t] * 0.125f);
            qa[kb][2] = f2tf32(Q0[kb * 8 + t + 4] * 0.125f);
            qa[kb][3] = f2tf32(Q8[kb * 8 + t + 4] * 0.125f);
        }
    }

    float O[8][4];
#pragma unroll
    for (int nt = 0; nt < 8; nt++)
#pragma unroll
        for (int i = 0; i < 4; i++) O[nt][i] = 0.f;
    float m0 = -INFINITY, m1 = -INFINITY, l0 = 0.f, l1 = 0.f;

    const int ntiles = (q0 + BQ) >> 6;
    for (int kt = 0; kt < ntiles; kt++) {
        const int k0 = kt << 6;
        __syncthreads();
#pragma unroll
        for (int i = 0; i < 4; i++) {
            int idx = tid + i * 256;
            int row = idx >> 4, c4 = idx & 15;
            const float* gk = qkv + base + (size_t)(k0 + row) * QKVC + hoff + c4 * 4;
            float4 kv = *(const float4*)(gk + CDIM);
            float4 vv = *(const float4*)(gk + 2 * CDIM);
            uint4 ku = make_uint4(f2tf32(kv.x), f2tf32(kv.y), f2tf32(kv.z), f2tf32(kv.w));
            uint4 vu = make_uint4(f2tf32(vv.x), f2tf32(vv.y), f2tf32(vv.z), f2tf32(vv.w));
            *(uint4*)&Ks[row * KS_STRIDE + c4 * 4] = ku;
            *(uint4*)&Vs[row * VS_STRIDE + c4 * 4] = vu;
        }
        __syncthreads();

        float S[8][4];
#pragma unroll
        for (int nt = 0; nt < 8; nt++)
#pragma unroll
            for (int i = 0; i < 4; i++) S[nt][i] = 0.f;

#pragma unroll
        for (int kb = 0; kb < 8; kb++) {
#pragma unroll
            for (int nt = 0; nt < 8; nt++) {
                const unsigned* kr = &Ks[(nt * 8 + g) * KS_STRIDE + kb * 8 + t];
                mma_tf32(S[nt], qa[kb][0], qa[kb][1], qa[kb][2], qa[kb][3],
                         kr[0], kr[4]);
            }
        }

        if (k0 + BKV - 1 > q0 + w * 16) {
#pragma unroll
            for (int nt = 0; nt < 8; nt++) {
                int col = k0 + nt * 8 + 2 * t;
                if (col > rowA)     S[nt][0] = -INFINITY;
                if (col + 1 > rowA) S[nt][1] = -INFINITY;
                if (col > rowA + 8)     S[nt][2] = -INFINITY;
                if (col + 1 > rowA + 8) S[nt][3] = -INFINITY;
            }
        }

        float mt0 = -INFINITY, mt1 = -INFINITY;
#pragma unroll
        for (int nt = 0; nt < 8; nt++) {
            mt0 = fmaxf(mt0, fmaxf(S[nt][0], S[nt][1]));
            mt1 = fmaxf(mt1, fmaxf(S[nt][2], S[nt][3]));
        }
#pragma unroll
        for (int off = 1; off < 4; off <<= 1) {
            mt0 = fmaxf(mt0, __shfl_xor_sync(0xffffffffu, mt0, off));
            mt1 = fmaxf(mt1, __shfl_xor_sync(0xffffffffu, mt1, off));
        }
        float mn0 = fmaxf(m0, mt0), mn1 = fmaxf(m1, mt1);
        float al0 = __expf(m0 - mn0), al1 = __expf(m1 - mn1);
        m0 = mn0; m1 = mn1;

        float ls0 = 0.f, ls1 = 0.f;
        unsigned* p0 = &Ps[(w * 16 + g) * PS_STRIDE + 2 * t];
        unsigned* p1 = p0 + 8 * PS_STRIDE;
#pragma unroll
        for (int nt = 0; nt < 8; nt++) {
            float e00 = __expf(S[nt][0] - mn0);
            float e01 = __expf(S[nt][1] - mn0);
            float e10 = __expf(S[nt][2] - mn1);
            float e11 = __expf(S[nt][3] - mn1);
            ls0 += e00 + e01;
            ls1 += e10 + e11;
            *(uint2*)&p0[nt * 8] = make_uint2(f2tf32(e00), f2tf32(e01));
            *(uint2*)&p1[nt * 8] = make_uint2(f2tf32(e10), f2tf32(e11));
        }
#pragma unroll
        for (int off = 1; off < 4; off <<= 1) {
            ls0 += __shfl_xor_sync(0xffffffffu, ls0, off);
            ls1 += __shfl_xor_sync(0xffffffffu, ls1, off);
        }
        l0 = l0 * al0 + ls0;
        l1 = l1 * al1 + ls1;
#pragma unroll
        for (int nt = 0; nt < 8; nt++) {
            O[nt][0] *= al0; O[nt][1] *= al0;
            O[nt][2] *= al1; O[nt][3] *= al1;
        }
        __syncwarp();

        const unsigned* pr0 = &Ps[(w * 16 + g) * PS_STRIDE];
        const unsigned* pr8 = pr0 + 8 * PS_STRIDE;
#pragma unroll
        for (int kb = 0; kb < 8; kb++) {
            unsigned pa0 = pr0[kb * 8 + t];
            unsigned pa1 = pr8[kb * 8 + t];
            unsigned pa2 = pr0[kb * 8 + t + 4];
            unsigned pa3 = pr8[kb * 8 + t + 4];
#pragma unroll
            for (int nt = 0; nt < 8; nt++) {
                const unsigned* vr = &Vs[(kb * 8 + t) * VS_STRIDE + nt * 8 + g];
                mma_tf32(O[nt], pa0, pa1, pa2, pa3, vr[0], vr[4 * VS_STRIDE]);
            }
        }
    }

    float inv0 = 1.f / l0, inv1 = 1.f / l1;
    float* y0 = y + ((size_t)b * SEQ + rowA) * CDIM + hoff;
    float* y1 = y0 + (size_t)8 * CDIM;
#pragma unroll
    for (int nt = 0; nt < 8; nt++) {
        *(float2*)&y0[nt * 8 + 2 * t] = make_float2(O[nt][0] * inv0, O[nt][1] * inv0);
        *(float2*)&y1[nt * 8 + 2 * t] = make_float2(O[nt][2] * inv1, O[nt][3] * inv1);
    }
}

// ---------------------------------------------------------------------------
extern "C" void kernel_launch(void* const* d_in, const int* in_sizes, int n_in,
                              void* d_out, int out_size)
{
    const float* x      = (const float*)d_in[0];
    const float* W_attn = (const float*)d_in[1];
    const float* b_attn = (const float*)d_in[2];
    const float* W_proj = (const float*)d_in[3];
    const float* b_proj = (const float*)d_in[4];
    float* out = (float*)d_out;

    float *qkv, *y;
    cudaGetSymbolAddress((void**)&qkv, g_qkv);
    cudaGetSymbolAddress((void**)&y,   g_y);

    cudaFuncSetAttribute(attn_tc, cudaFuncAttributeMaxDynamicSharedMemorySize,
                         ATTN_SMEM);

    // 1) qkv = x @ W_attn + b_attn          [8192,3072]
    gemm_tf32<<<dim3(QKVC / 128, ROWS / 128), 256>>>(x, W_attn, b_attn, qkv,
                                                     ROWS, QKVC, CDIM);
    // 2) attention -> y                     [8192,1024]
    attn_tc<<<dim3(SEQ / BQ, NH, BATCH), 256, ATTN_SMEM>>>(qkv, y);
    // 3) out = y @ W_proj + b_proj          [8192,1024]
    gemm_tf32<<<dim3(CDIM / 128, ROWS / 128), 256>>>(y, W_proj, b_proj, out,
                                                     ROWS, CDIM, CDIM);
}

// round 6
// speedup vs baseline: 1.2249x; 1.2249x over previous
#include <cuda_runtime.h>
#include <math.h>

// Problem constants
#define BATCH 4
#define SEQ   2048
#define CDIM  1024
#define NH    16
#define HD    64
#define ROWS  (BATCH*SEQ)      // 8192
#define QKVC  (3*CDIM)         // 3072

// Scratch (allocation-free rule: __device__ globals)
__device__ float g_qkv[(size_t)ROWS * QKVC];  // [B*T, 3C]  q|k|v (tf32-rounded)
__device__ float g_y[(size_t)ROWS * CDIM];    // attn out (tf32-rounded)
__device__ float g_xc[(size_t)ROWS * CDIM];   // x,  tf32-rounded
__device__ float g_wa[(size_t)CDIM * QKVC];   // W_attn, tf32-rounded
__device__ float g_wp[(size_t)CDIM * CDIM];   // W_proj, tf32-rounded

__device__ __forceinline__ unsigned f2tf32(float f) {
    unsigned r;
    asm("cvt.rna.tf32.f32 %0, %1;" : "=r"(r) : "f"(f));
    return r;
}
__device__ __forceinline__ float tf32r(float f) {
    return __uint_as_float(f2tf32(f));
}

__device__ __forceinline__ void mma_tf32(float c[4], unsigned a0, unsigned a1,
                                         unsigned a2, unsigned a3,
                                         unsigned b0, unsigned b1) {
    asm volatile(
        "mma.sync.aligned.m16n8k8.row.col.f32.tf32.tf32.f32 "
        "{%0,%1,%2,%3}, {%4,%5,%6,%7}, {%8,%9}, {%0,%1,%2,%3};\n"
        : "+f"(c[0]), "+f"(c[1]), "+f"(c[2]), "+f"(c[3])
        : "r"(a0), "r"(a1), "r"(a2), "r"(a3), "r"(b0), "r"(b1));
}

__device__ __forceinline__ void cp16(unsigned smem_addr, const void* gptr) {
    asm volatile("cp.async.cg.shared.global [%0], [%1], 16;\n"
                 :: "r"(smem_addr), "l"(gptr));
}

// ---------------------------------------------------------------------------
// Pre-pass: round fp32 array to tf32 bit pattern (vectorized, coalesced).
// ---------------------------------------------------------------------------
__global__ __launch_bounds__(256)
void round_tf32(const float* __restrict__ in, float* __restrict__ out, int n4)
{
    int i = blockIdx.x * blockDim.x + threadIdx.x;
    if (i < n4) {
        float4 v = ((const float4*)in)[i];
        v.x = tf32r(v.x); v.y = tf32r(v.y); v.z = tf32r(v.z); v.w = tf32r(v.w);
        ((float4*)out)[i] = v;
    }
}

// ---------------------------------------------------------------------------
// tf32 tensor-core GEMM + bias. Inputs MUST be pre-rounded to tf32 bits.
// C[M,N] = A[M,K] @ B[K,N] + bias[N]; optional tf32 rounding of the output.
// Block 128x128x16, 256 thr = 8 warps (2x4), warp 64x32, thread 4x4 mma tiles.
// cp.async double-buffered smem, zero conversions in the mainloop.
// ---------------------------------------------------------------------------
#define AS_STRIDE 20    // 16 + 4 pad
#define BS_STRIDE 136   // 128 + 8 pad

__global__ __launch_bounds__(256)
void gemm_tf32(const float* __restrict__ A, const float* __restrict__ B,
               const float* __restrict__ bias, float* __restrict__ C,
               int M, int N, int K, int roundOut)
{
    __shared__ float As[2][128 * AS_STRIDE];
    __shared__ float Bs[2][16 * BS_STRIDE];

    const int tid   = threadIdx.x;
    const int wid   = tid >> 5;
    const int lane  = tid & 31;
    const int warpM = wid >> 2;
    const int warpN = wid & 3;
    const int group = lane >> 2;
    const int tig   = lane & 3;

    const int rowBase = blockIdx.y * 128;
    const int colBase = blockIdx.x * 128;

    const int aRow = tid >> 2;
    const int aC4  = tid & 3;
    const int bRow = tid >> 5;
    const int bC4  = tid & 31;

    const unsigned sAs0 = (unsigned)__cvta_generic_to_shared(&As[0][0]);
    const unsigned sAs1 = (unsigned)__cvta_generic_to_shared(&As[1][0]);
    const unsigned sBs0 = (unsigned)__cvta_generic_to_shared(&Bs[0][0]);
    const unsigned sBs1 = (unsigned)__cvta_generic_to_shared(&Bs[1][0]);

    float acc[4][4][4];
#pragma unroll
    for (int mt = 0; mt < 4; mt++)
#pragma unroll
        for (int nt = 0; nt < 4; nt++)
#pragma unroll
            for (int i = 0; i < 4; i++) acc[mt][nt][i] = 0.f;

    const int nTiles = K >> 4;

    auto loadTile = [&](int s, int k0) {
        unsigned sA = s ? sAs1 : sAs0;
        unsigned sB = s ? sBs1 : sBs0;
#pragma unroll
        for (int i = 0; i < 2; i++) {
            int row = aRow + i * 64;
            cp16(sA + (row * AS_STRIDE + aC4 * 4) * 4,
                 A + (size_t)(rowBase + row) * K + k0 + aC4 * 4);
        }
#pragma unroll
        for (int i = 0; i < 2; i++) {
            int row = bRow + i * 8;
            cp16(sB + (row * BS_STRIDE + bC4 * 4) * 4,
                 B + (size_t)(k0 + row) * N + colBase + bC4 * 4);
        }
    };

    loadTile(0, 0);
    asm volatile("cp.async.commit_group;\n" ::);

    for (int kt = 0; kt < nTiles; kt++) {
        asm volatile("cp.async.wait_group 0;\n" ::);
        __syncthreads();

        int nxt = kt + 1;
        if (nxt < nTiles) loadTile(nxt & 1, nxt << 4);
        asm volatile("cp.async.commit_group;\n" ::);

        const unsigned* as = (const unsigned*)As[kt & 1];
        const unsigned* bs = (const unsigned*)Bs[kt & 1];

#pragma unroll
        for (int ks = 0; ks < 2; ks++) {
            const int kb = ks * 8;
            unsigned af[4][4];
#pragma unroll
            for (int mt = 0; mt < 4; mt++) {
                int r = warpM * 64 + mt * 16 + group;
                af[mt][0] = as[(r + 0) * AS_STRIDE + kb + tig];
                af[mt][1] = as[(r + 8) * AS_STRIDE + kb + tig];
                af[mt][2] = as[(r + 0) * AS_STRIDE + kb + tig + 4];
                af[mt][3] = as[(r + 8) * AS_STRIDE + kb + tig + 4];
            }
            unsigned bf[4][2];
#pragma unroll
            for (int nt = 0; nt < 4; nt++) {
                int c = warpN * 32 + nt * 8 + group;
                bf[nt][0] = bs[(kb + tig + 0) * BS_STRIDE + c];
                bf[nt][1] = bs[(kb + tig + 4) * BS_STRIDE + c];
            }
#pragma unroll
            for (int mt = 0; mt < 4; mt++)
#pragma unroll
                for (int nt = 0; nt < 4; nt++)
                    mma_tf32(acc[mt][nt], af[mt][0], af[mt][1], af[mt][2],
                             af[mt][3], bf[nt][0], bf[nt][1]);
        }
        __syncthreads();
    }

#pragma unroll
    for (int mt = 0; mt < 4; mt++) {
        int r0 = rowBase + warpM * 64 + mt * 16 + group;
#pragma unroll
        for (int nt = 0; nt < 4; nt++) {
            int c = colBase + warpN * 32 + nt * 8 + 2 * tig;
            float b0 = bias[c], b1 = bias[c + 1];
            float o00 = acc[mt][nt][0] + b0, o01 = acc[mt][nt][1] + b1;
            float o10 = acc[mt][nt][2] + b0, o11 = acc[mt][nt][3] + b1;
            if (roundOut) {
                o00 = tf32r(o00); o01 = tf32r(o01);
                o10 = tf32r(o10); o11 = tf32r(o11);
            }
            *(float2*)&C[(size_t)(r0 + 0) * N + c] = make_float2(o00, o01);
            *(float2*)&C[(size_t)(r0 + 8) * N + c] = make_float2(o10, o11);
        }
    }
}

// ---------------------------------------------------------------------------
// Tensor-core flash attention. qkv is pre-rounded tf32 -> loaders copy raw
// bits (no cvt). Only P (exp output) needs conversion. y written tf32-rounded.
// ---------------------------------------------------------------------------
#define BQ 128
#define BKV 64
#define KS_STRIDE 68
#define VS_STRIDE 72
#define PS_STRIDE 68
#define ATTN_SMEM ((BKV*KS_STRIDE + BKV*VS_STRIDE + BQ*PS_STRIDE) * 4)

__global__ __launch_bounds__(256)
void attn_tc(const float* __restrict__ qkv, float* __restrict__ y)
{
    extern __shared__ unsigned smem[];
    unsigned* Ks = smem;
    unsigned* Vs = Ks + BKV * KS_STRIDE;
    unsigned* Ps = Vs + BKV * VS_STRIDE;

    const int q0 = blockIdx.x * BQ;
    const int h  = blockIdx.y;
    const int b  = blockIdx.z;

    const int tid  = threadIdx.x;
    const int w    = tid >> 5;
    const int lane = tid & 31;
    const int g    = lane >> 2;
    const int t    = lane & 3;

    const size_t base = (size_t)b * SEQ * QKVC;
    const int hoff = h * HD;
    const int rowA = q0 + w * 16 + g;

    // Q fragments: pre-rounded tf32; *0.125f is a power of 2 (mantissa-exact)
    unsigned qa[8][4];
    {
        const float* Q0 = qkv + base + (size_t)rowA * QKVC + hoff;
        const float* Q8 = Q0 + (size_t)8 * QKVC;
#pragma unroll
        for (int kb = 0; kb < 8; kb++) {
            qa[kb][0] = __float_as_uint(Q0[kb * 8 + t] * 0.125f);
            qa[kb][1] = __float_as_uint(Q8[kb * 8 + t] * 0.125f);
            qa[kb][2] = __float_as_uint(Q0[kb * 8 + t + 4] * 0.125f);
            qa[kb][3] = __float_as_uint(Q8[kb * 8 + t + 4] * 0.125f);
        }
    }

    float O[8][4];
#pragma unroll
    for (int nt = 0; nt < 8; nt++)
#pragma unroll
        for (int i = 0; i < 4; i++) O[nt][i] = 0.f;
    float m0 = -INFINITY, m1 = -INFINITY, l0 = 0.f, l1 = 0.f;

    const int ntiles = (q0 + BQ) >> 6;
    for (int kt = 0; kt < ntiles; kt++) {
        const int k0 = kt << 6;
        __syncthreads();
        // raw bit copy (pre-rounded): no conversions
#pragma unroll
        for (int i = 0; i < 4; i++) {
            int idx = tid + i * 256;
            int row = idx >> 4, c4 = idx & 15;
            const float* gk = qkv + base + (size_t)(k0 + row) * QKVC + hoff + c4 * 4;
            *(uint4*)&Ks[row * KS_STRIDE + c4 * 4] = *(const uint4*)(gk + CDIM);
            *(uint4*)&Vs[row * VS_STRIDE + c4 * 4] = *(const uint4*)(gk + 2 * CDIM);
        }
        __syncthreads();

        float S[8][4];
#pragma unroll
        for (int nt = 0; nt < 8; nt++)
#pragma unroll
            for (int i = 0; i < 4; i++) S[nt][i] = 0.f;

#pragma unroll
        for (int kb = 0; kb < 8; kb++) {
#pragma unroll
            for (int nt = 0; nt < 8; nt++) {
                const unsigned* kr = &Ks[(nt * 8 + g) * KS_STRIDE + kb * 8 + t];
                mma_tf32(S[nt], qa[kb][0], qa[kb][1], qa[kb][2], qa[kb][3],
                         kr[0], kr[4]);
            }
        }

        if (k0 + BKV - 1 > q0 + w * 16) {
#pragma unroll
            for (int nt = 0; nt < 8; nt++) {
                int col = k0 + nt * 8 + 2 * t;
                if (col > rowA)     S[nt][0] = -INFINITY;
                if (col + 1 > rowA) S[nt][1] = -INFINITY;
                if (col > rowA + 8)     S[nt][2] = -INFINITY;
                if (col + 1 > rowA + 8) S[nt][3] = -INFINITY;
            }
        }

        float mt0 = -INFINITY, mt1 = -INFINITY;
#pragma unroll
        for (int nt = 0; nt < 8; nt++) {
            mt0 = fmaxf(mt0, fmaxf(S[nt][0], S[nt][1]));
            mt1 = fmaxf(mt1, fmaxf(S[nt][2], S[nt][3]));
        }
#pragma unroll
        for (int off = 1; off < 4; off <<= 1) {
            mt0 = fmaxf(mt0, __shfl_xor_sync(0xffffffffu, mt0, off));
            mt1 = fmaxf(mt1, __shfl_xor_sync(0xffffffffu, mt1, off));
        }
        float mn0 = fmaxf(m0, mt0), mn1 = fmaxf(m1, mt1);
        float al0 = __expf(m0 - mn0), al1 = __expf(m1 - mn1);
        m0 = mn0; m1 = mn1;

        float ls0 = 0.f, ls1 = 0.f;
        unsigned* p0 = &Ps[(w * 16 + g) * PS_STRIDE + 2 * t];
        unsigned* p1 = p0 + 8 * PS_STRIDE;
#pragma unroll
        for (int nt = 0; nt < 8; nt++) {
            float e00 = __expf(S[nt][0] - mn0);
            float e01 = __expf(S[nt][1] - mn0);
            float e10 = __expf(S[nt][2] - mn1);
            float e11 = __expf(S[nt][3] - mn1);
            ls0 += e00 + e01;
            ls1 += e10 + e11;
            *(uint2*)&p0[nt * 8] = make_uint2(f2tf32(e00), f2tf32(e01));
            *(uint2*)&p1[nt * 8] = make_uint2(f2tf32(e10), f2tf32(e11));
        }
#pragma unroll
        for (int off = 1; off < 4; off <<= 1) {
            ls0 += __shfl_xor_sync(0xffffffffu, ls0, off);
            ls1 += __shfl_xor_sync(0xffffffffu, ls1, off);
        }
        l0 = l0 * al0 + ls0;
        l1 = l1 * al1 + ls1;
#pragma unroll
        for (int nt = 0; nt < 8; nt++) {
            O[nt][0] *= al0; O[nt][1] *= al0;
            O[nt][2] *= al1; O[nt][3] *= al1;
        }
        __syncwarp();

        const unsigned* pr0 = &Ps[(w * 16 + g) * PS_STRIDE];
        const unsigned* pr8 = pr0 + 8 * PS_STRIDE;
#pragma unroll
        for (int kb = 0; kb < 8; kb++) {
            unsigned pa0 = pr0[kb * 8 + t];
            unsigned pa1 = pr8[kb * 8 + t];
            unsigned pa2 = pr0[kb * 8 + t + 4];
            unsigned pa3 = pr8[kb * 8 + t + 4];
#pragma unroll
            for (int nt = 0; nt < 8; nt++) {
                const unsigned* vr = &Vs[(kb * 8 + t) * VS_STRIDE + nt * 8 + g];
                mma_tf32(O[nt], pa0, pa1, pa2, pa3, vr[0], vr[4 * VS_STRIDE]);
            }
        }
    }

    // normalize + write tf32-rounded (proj gemm consumes raw bits)
    float inv0 = 1.f / l0, inv1 = 1.f / l1;
    float* y0 = y + ((size_t)b * SEQ + rowA) * CDIM + hoff;
    float* y1 = y0 + (size_t)8 * CDIM;
#pragma unroll
    for (int nt = 0; nt < 8; nt++) {
        *(float2*)&y0[nt * 8 + 2 * t] =
            make_float2(tf32r(O[nt][0] * inv0), tf32r(O[nt][1] * inv0));
        *(float2*)&y1[nt * 8 + 2 * t] =
            make_float2(tf32r(O[nt][2] * inv1), tf32r(O[nt][3] * inv1));
    }
}

// ---------------------------------------------------------------------------
extern "C" void kernel_launch(void* const* d_in, const int* in_sizes, int n_in,
                              void* d_out, int out_size)
{
    const float* x      = (const float*)d_in[0];
    const float* W_attn = (const float*)d_in[1];
    const float* b_attn = (const float*)d_in[2];
    const float* W_proj = (const float*)d_in[3];
    const float* b_proj = (const float*)d_in[4];
    float* out = (float*)d_out;

    float *qkv, *y, *xc, *wa, *wp;
    cudaGetSymbolAddress((void**)&qkv, g_qkv);
    cudaGetSymbolAddress((void**)&y,   g_y);
    cudaGetSymbolAddress((void**)&xc,  g_xc);
    cudaGetSymbolAddress((void**)&wa,  g_wa);
    cudaGetSymbolAddress((void**)&wp,  g_wp);

    cudaFuncSetAttribute(attn_tc, cudaFuncAttributeMaxDynamicSharedMemorySize,
                         ATTN_SMEM);

    // 0) pre-round operands to tf32 bit patterns
    {
        int n4x = ROWS * CDIM / 4;
        int n4a = CDIM * QKVC / 4;
        int n4p = CDIM * CDIM / 4;
        round_tf32<<<(n4x + 255) / 256, 256>>>(x, xc, n4x);
        round_tf32<<<(n4a + 255) / 256, 256>>>(W_attn, wa, n4a);
        round_tf32<<<(n4p + 255) / 256, 256>>>(W_proj, wp, n4p);
    }

    // 1) qkv = xc @ wa + b_attn  (output tf32-rounded)   [8192,3072]
    gemm_tf32<<<dim3(QKVC / 128, ROWS / 128), 256>>>(xc, wa, b_attn, qkv,
                                                     ROWS, QKVC, CDIM, 1);
    // 2) attention -> y (tf32-rounded)                   [8192,1024]
    attn_tc<<<dim3(SEQ / BQ, NH, BATCH), 256, ATTN_SMEM>>>(qkv, y);
    // 3) out = y @ wp + b_proj  (full fp32 output)       [8192,1024]
    gemm_tf32<<<dim3(CDIM / 128, ROWS / 128), 256>>>(y, wp, b_proj, out,
                                                     ROWS, CDIM, CDIM, 0);
}

// round 8
// speedup vs baseline: 1.2361x; 1.0092x over previous
#include <cuda_runtime.h>
#include <math.h>

// Problem constants
#define BATCH 4
#define SEQ   2048
#define CDIM  1024
#define NH    16
#define HD    64
#define ROWS  (BATCH*SEQ)      // 8192
#define QKVC  (3*CDIM)         // 3072

// Scratch (allocation-free rule: __device__ globals)
__device__ float g_qkv[(size_t)ROWS * QKVC];  // q|k|v (tf32-rounded)
__device__ float g_y[(size_t)ROWS * CDIM];    // attn out (tf32-rounded)
__device__ float g_xc[(size_t)ROWS * CDIM];   // x,  tf32-rounded
__device__ float g_wa[(size_t)CDIM * QKVC];   // W_attn, tf32-rounded
__device__ float g_wp[(size_t)CDIM * CDIM];   // W_proj, tf32-rounded

__device__ __forceinline__ unsigned f2tf32(float f) {
    unsigned r;
    asm("cvt.rna.tf32.f32 %0, %1;" : "=r"(r) : "f"(f));
    return r;
}
__device__ __forceinline__ float tf32r(float f) {
    return __uint_as_float(f2tf32(f));
}

__device__ __forceinline__ void mma_tf32(float c[4], unsigned a0, unsigned a1,
                                         unsigned a2, unsigned a3,
                                         unsigned b0, unsigned b1) {
    asm volatile(
        "mma.sync.aligned.m16n8k8.row.col.f32.tf32.tf32.f32 "
        "{%0,%1,%2,%3}, {%4,%5,%6,%7}, {%8,%9}, {%0,%1,%2,%3};\n"
        : "+f"(c[0]), "+f"(c[1]), "+f"(c[2]), "+f"(c[3])
        : "r"(a0), "r"(a1), "r"(a2), "r"(a3), "r"(b0), "r"(b1));
}

__device__ __forceinline__ void cp16(unsigned smem_addr, const void* gptr) {
    asm volatile("cp.async.cg.shared.global [%0], [%1], 16;\n"
                 :: "r"(smem_addr), "l"(gptr));
}
__device__ __forceinline__ void cp_commit() {
    asm volatile("cp.async.commit_group;\n" ::);
}

// ---------------------------------------------------------------------------
// Pre-pass: round fp32 array to tf32 bit pattern (vectorized, coalesced).
// ---------------------------------------------------------------------------
__global__ __launch_bounds__(256)
void round_tf32(const float* __restrict__ in, float* __restrict__ out, int n4)
{
    int i = blockIdx.x * blockDim.x + threadIdx.x;
    if (i < n4) {
        float4 v = ((const float4*)in)[i];
        v.x = tf32r(v.x); v.y = tf32r(v.y); v.z = tf32r(v.z); v.w = tf32r(v.w);
        ((float4*)out)[i] = v;
    }
}

// ---------------------------------------------------------------------------
// tf32 tensor-core GEMM + bias. Inputs pre-rounded to tf32 bits.
// 3-stage cp.async pipeline, ONE __syncthreads per k-tile.
// Block 128x128x16, 256 thr = 8 warps (2x4), warp 64x32.
// ---------------------------------------------------------------------------
#define AS_STRIDE 20            // 16 + 4 pad
#define BS_STRIDE 136           // 128 + 8 pad
#define AS_SZ (128 * AS_STRIDE) // floats per stage
#define BS_SZ (16 * BS_STRIDE)
#define GEMM_SMEM (3 * (AS_SZ + BS_SZ) * 4)

__global__ __launch_bounds__(256)
void gemm_tf32(const float* __restrict__ A, const float* __restrict__ B,
               const float* __restrict__ bias, float* __restrict__ C,
               int M, int N, int K, int roundOut)
{
    extern __shared__ float sm[];
    float* Asm = sm;                 // [3][AS_SZ]
    float* Bsm = sm + 3 * AS_SZ;     // [3][BS_SZ]

    const int tid   = threadIdx.x;
    const int wid   = tid >> 5;
    const int lane  = tid & 31;
    const int warpM = wid >> 2;
    const int warpN = wid & 3;
    const int group = lane >> 2;
    const int tig   = lane & 3;

    const int rowBase = blockIdx.y * 128;
    const int colBase = blockIdx.x * 128;

    const int aRow = tid >> 2;
    const int aC4  = tid & 3;
    const int bRow = tid >> 5;
    const int bC4  = tid & 31;

    const unsigned sAb = (unsigned)__cvta_generic_to_shared(Asm);
    const unsigned sBb = (unsigned)__cvta_generic_to_shared(Bsm);

    float acc[4][4][4];
#pragma unroll
    for (int mt = 0; mt < 4; mt++)
#pragma unroll
        for (int nt = 0; nt < 4; nt++)
#pragma unroll
            for (int i = 0; i < 4; i++) acc[mt][nt][i] = 0.f;

    const int nTiles = K >> 4;

    auto loadTile = [&](int s, int k0) {
        unsigned sA = sAb + s * AS_SZ * 4;
        unsigned sB = sBb + s * BS_SZ * 4;
#pragma unroll
        for (int i = 0; i < 2; i++) {
            int row = aRow + i * 64;
            cp16(sA + (row * AS_STRIDE + aC4 * 4) * 4,
                 A + (size_t)(rowBase + row) * K + k0 + aC4 * 4);
        }
#pragma unroll
        for (int i = 0; i < 2; i++) {
            int row = bRow + i * 8;
            cp16(sB + (row * BS_STRIDE + bC4 * 4) * 4,
                 B + (size_t)(k0 + row) * N + colBase + bC4 * 4);
        }
    };

    // prologue: 2 stages in flight
    loadTile(0, 0);  cp_commit();
    loadTile(1, 16); cp_commit();

    for (int kt = 0; kt < nTiles; kt++) {
        asm volatile("cp.async.wait_group 1;\n" ::);   // stage kt ready
        __syncthreads();
        // prefetch stage kt+2 (slot (kt+2)%3 != reading slot kt%3;
        // prior readers of that slot passed the sync above)
        if (kt + 2 < nTiles) loadTile((kt + 2) % 3, (kt + 2) << 4);
        cp_commit();                                    // always (tail-safe)

        const int st = kt % 3;
        const unsigned* as = (const unsigned*)(Asm + st * AS_SZ);
        const unsigned* bs = (const unsigned*)(Bsm + st * BS_SZ);

#pragma unroll
        for (int ks = 0; ks < 2; ks++) {
            const int kb = ks * 8;
            unsigned af[4][4];
#pragma unroll
            for (int mt = 0; mt < 4; mt++) {
                int r = warpM * 64 + mt * 16 + group;
                af[mt][0] = as[(r + 0) * AS_STRIDE + kb + tig];
                af[mt][1] = as[(r + 8) * AS_STRIDE + kb + tig];
                af[mt][2] = as[(r + 0) * AS_STRIDE + kb + tig + 4];
                af[mt][3] = as[(r + 8) * AS_STRIDE + kb + tig + 4];
            }
            unsigned bf[4][2];
#pragma unroll
            for (int nt = 0; nt < 4; nt++) {
                int c = warpN * 32 + nt * 8 + group;
                bf[nt][0] = bs[(kb + tig + 0) * BS_STRIDE + c];
                bf[nt][1] = bs[(kb + tig + 4) * BS_STRIDE + c];
            }
#pragma unroll
            for (int mt = 0; mt < 4; mt++)
#pragma unroll
                for (int nt = 0; nt < 4; nt++)
                    mma_tf32(acc[mt][nt], af[mt][0], af[mt][1], af[mt][2],
                             af[mt][3], bf[nt][0], bf[nt][1]);
        }
        // no trailing sync: next iteration's sync protects slot reuse
    }

#pragma unroll
    for (int mt = 0; mt < 4; mt++) {
        int r0 = rowBase + warpM * 64 + mt * 16 + group;
#pragma unroll
        for (int nt = 0; nt < 4; nt++) {
            int c = colBase + warpN * 32 + nt * 8 + 2 * tig;
            float b0 = bias[c], b1 = bias[c + 1];
            float o00 = acc[mt][nt][0] + b0, o01 = acc[mt][nt][1] + b1;
            float o10 = acc[mt][nt][2] + b0, o11 = acc[mt][nt][3] + b1;
            if (roundOut) {
                o00 = tf32r(o00); o01 = tf32r(o01);
                o10 = tf32r(o10); o11 = tf32r(o11);
            }
            *(float2*)&C[(size_t)(r0 + 0) * N + c] = make_float2(o00, o01);
            *(float2*)&C[(size_t)(r0 + 8) * N + c] = make_float2(o10, o11);
        }
    }
}

// ---------------------------------------------------------------------------
// Tensor-core flash attention. cp.async double-buffered K/V, one sync per
// tile, per-warp skip of fully-masked tiles (bit-exact: identity update).
// ---------------------------------------------------------------------------
#define BQ 128
#define BKV 64
#define KS_STRIDE 68
#define VS_STRIDE 72
#define PS_STRIDE 68
#define KS_SZ (BKV * KS_STRIDE)
#define VS_SZ (BKV * VS_STRIDE)
#define ATTN_SMEM ((2*KS_SZ + 2*VS_SZ + BQ*PS_STRIDE) * 4)

__global__ __launch_bounds__(256)
void attn_tc(const float* __restrict__ qkv, float* __restrict__ y)
{
    extern __shared__ unsigned smem[];
    unsigned* Ks = smem;                    // [2][KS_SZ]
    unsigned* Vs = smem + 2 * KS_SZ;        // [2][VS_SZ]
    unsigned* Ps = Vs + 2 * VS_SZ;          // [BQ][PS_STRIDE]

    const int q0 = blockIdx.x * BQ;
    const int h  = blockIdx.y;
    const int b  = blockIdx.z;

    const int tid  = threadIdx.x;
    const int w    = tid >> 5;
    const int lane = tid & 31;
    const int g    = lane >> 2;
    const int t    = lane & 3;

    const size_t base = (size_t)b * SEQ * QKVC;
    const int hoff = h * HD;
    const int rowA = q0 + w * 16 + g;

    const unsigned ksb = (unsigned)__cvta_generic_to_shared(Ks);
    const unsigned vsb = (unsigned)__cvta_generic_to_shared(Vs);

    auto loadKV = [&](int s, int k0) {
        unsigned kb_ = ksb + s * KS_SZ * 4;
        unsigned vb_ = vsb + s * VS_SZ * 4;
#pragma unroll
        for (int i = 0; i < 4; i++) {
            int idx = tid + i * 256;
            int row = idx >> 4, c4 = idx & 15;
            const float* gk = qkv + base + (size_t)(k0 + row) * QKVC + hoff + c4 * 4;
            cp16(kb_ + (row * KS_STRIDE + c4 * 4) * 4, gk + CDIM);
            cp16(vb_ + (row * VS_STRIDE + c4 * 4) * 4, gk + 2 * CDIM);
        }
    };

    // Q fragments (pre-rounded tf32; *0.125f is exp-only, mantissa-exact)
    unsigned qa[8][4];
    {
        const float* Q0 = qkv + base + (size_t)rowA * QKVC + hoff;
        const float* Q8 = Q0 + (size_t)8 * QKVC;
#pragma unroll
        for (int kb = 0; kb < 8; kb++) {
            qa[kb][0] = __float_as_uint(Q0[kb * 8 + t] * 0.125f);
            qa[kb][1] = __float_as_uint(Q8[kb * 8 + t] * 0.125f);
            qa[kb][2] = __float_as_uint(Q0[kb * 8 + t + 4] * 0.125f);
            qa[kb][3] = __float_as_uint(Q8[kb * 8 + t + 4] * 0.125f);
        }
    }

    float O[8][4];
#pragma unroll
    for (int nt = 0; nt < 8; nt++)
#pragma unroll
        for (int i = 0; i < 4; i++) O[nt][i] = 0.f;
    float m0 = -INFINITY, m1 = -INFINITY, l0 = 0.f, l1 = 0.f;

    const int ntiles = (q0 + BQ) >> 6;

    loadKV(0, 0); cp_commit();

    for (int kt = 0; kt < ntiles; kt++) {
        const int k0 = kt << 6;
        asm volatile("cp.async.wait_group 0;\n" ::);   // tile kt in smem
        __syncthreads();
        if (kt + 1 < ntiles) loadKV((kt + 1) & 1, (kt + 1) << 6);
        cp_commit();

        // Fully-masked tile for this warp => exact identity update: skip.
        if (k0 > q0 + w * 16 + 15) continue;

        const unsigned* ks_ = Ks + (kt & 1) * KS_SZ;
        const unsigned* vs_ = Vs + (kt & 1) * VS_SZ;

        float S[8][4];
#pragma unroll
        for (int nt = 0; nt < 8; nt++)
#pragma unroll
            for (int i = 0; i < 4; i++) S[nt][i] = 0.f;

#pragma unroll
        for (int kb = 0; kb < 8; kb++) {
#pragma unroll
            for (int nt = 0; nt < 8; nt++) {
                const unsigned* kr = &ks_[(nt * 8 + g) * KS_STRIDE + kb * 8 + t];
                mma_tf32(S[nt], qa[kb][0], qa[kb][1], qa[kb][2], qa[kb][3],
                         kr[0], kr[4]);
            }
        }

        if (k0 + BKV - 1 > q0 + w * 16) {
#pragma unroll
            for (int nt = 0; nt < 8; nt++) {
                int col = k0 + nt * 8 + 2 * t;
                if (col > rowA)     S[nt][0] = -INFINITY;
                if (col + 1 > rowA) S[nt][1] = -INFINITY;
                if (col > rowA + 8)     S[nt][2] = -INFINITY;
                if (col + 1 > rowA + 8) S[nt][3] = -INFINITY;
            }
        }

        float mt0 = -INFINITY, mt1 = -INFINITY;
#pragma unroll
        for (int nt = 0; nt < 8; nt++) {
            mt0 = fmaxf(mt0, fmaxf(S[nt][0], S[nt][1]));
            mt1 = fmaxf(mt1, fmaxf(S[nt][2], S[nt][3]));
        }
#pragma unroll
        for (int off = 1; off < 4; off <<= 1) {
            mt0 = fmaxf(mt0, __shfl_xor_sync(0xffffffffu, mt0, off));
            mt1 = fmaxf(mt1, __shfl_xor_sync(0xffffffffu, mt1, off));
        }
        float mn0 = fmaxf(m0, mt0), mn1 = fmaxf(m1, mt1);
        float al0 = __expf(m0 - mn0), al1 = __expf(m1 - mn1);
        m0 = mn0; m1 = mn1;

        float ls0 = 0.f, ls1 = 0.f;
        unsigned* p0 = &Ps[(w * 16 + g) * PS_STRIDE + 2 * t];
        unsigned* p1 = p0 + 8 * PS_STRIDE;
#pragma unroll
        for (int nt = 0; nt < 8; nt++) {
            float e00 = __expf(S[nt][0] - mn0);
            float e01 = __expf(S[nt][1] - mn0);
            float e10 = __expf(S[nt][2] - mn1);
            float e11 = __expf(S[nt][3] - mn1);
            ls0 += e00 + e01;
            ls1 += e10 + e11;
            *(uint2*)&p0[nt * 8] = make_uint2(f2tf32(e00), f2tf32(e01));
            *(uint2*)&p1[nt * 8] = make_uint2(f2tf32(e10), f2tf32(e11));
        }
#pragma unroll
        for (int off = 1; off < 4; off <<= 1) {
            ls0 += __shfl_xor_sync(0xffffffffu, ls0, off);
            ls1 += __shfl_xor_sync(0xffffffffu, ls1, off);
        }
        l0 = l0 * al0 + ls0;
        l1 = l1 * al1 + ls1;
#pragma unroll
        for (int nt = 0; nt < 8; nt++) {
            O[nt][0] *= al0; O[nt][1] *= al0;
            O[nt][2] *= al1; O[nt][3] *= al1;
        }
        __syncwarp();

        const unsigned* pr0 = &Ps[(w * 16 + g) * PS_STRIDE];
        const unsigned* pr8 = pr0 + 8 * PS_STRIDE;
#pragma unroll
        for (int kb = 0; kb < 8; kb++) {
            unsigned pa0 = pr0[kb * 8 + t];
            unsigned pa1 = pr8[kb * 8 + t];
            unsigned pa2 = pr0[kb * 8 + t + 4];
            unsigned pa3 = pr8[kb * 8 + t + 4];
#pragma unroll
            for (int nt = 0; nt < 8; nt++) {
                const unsigned* vr = &vs_[(kb * 8 + t) * VS_STRIDE + nt * 8 + g];
                mma_tf32(O[nt], pa0, pa1, pa2, pa3, vr[0], vr[4 * VS_STRIDE]);
            }
        }
    }

    // normalize + write tf32-rounded (proj gemm consumes raw bits)
    float inv0 = 1.f / l0, inv1 = 1.f / l1;
    float* y0 = y + ((size_t)b * SEQ + rowA) * CDIM + hoff;
    float* y1 = y0 + (size_t)8 * CDIM;
#pragma unroll
    for (int nt = 0; nt < 8; nt++) {
        *(float2*)&y0[nt * 8 + 2 * t] =
            make_float2(tf32r(O[nt][0] * inv0), tf32r(O[nt][1] * inv0));
        *(float2*)&y1[nt * 8 + 2 * t] =
            make_float2(tf32r(O[nt][2] * inv1), tf32r(O[nt][3] * inv1));
    }
}

// ---------------------------------------------------------------------------
extern "C" void kernel_launch(void* const* d_in, const int* in_sizes, int n_in,
                              void* d_out, int out_size)
{
    const float* x      = (const float*)d_in[0];
    const float* W_attn = (const float*)d_in[1];
    const float* b_attn = (const float*)d_in[2];
    const float* W_proj = (const float*)d_in[3];
    const float* b_proj = (const float*)d_in[4];
    float* out = (float*)d_out;

    float *qkv, *y, *xc, *wa, *wp;
    cudaGetSymbolAddress((void**)&qkv, g_qkv);
    cudaGetSymbolAddress((void**)&y,   g_y);
    cudaGetSymbolAddress((void**)&xc,  g_xc);
    cudaGetSymbolAddress((void**)&wa,  g_wa);
    cudaGetSymbolAddress((void**)&wp,  g_wp);

    cudaFuncSetAttribute(gemm_tf32, cudaFuncAttributeMaxDynamicSharedMemorySize,
                         GEMM_SMEM);
    cudaFuncSetAttribute(attn_tc, cudaFuncAttributeMaxDynamicSharedMemorySize,
                         ATTN_SMEM);

    // 0) pre-round operands to tf32 bit patterns
    {
        int n4x = ROWS * CDIM / 4;
        int n4a = CDIM * QKVC / 4;
        int n4p = CDIM * CDIM / 4;
        round_tf32<<<(n4x + 255) / 256, 256>>>(x, xc, n4x);
        round_tf32<<<(n4a + 255) / 256, 256>>>(W_attn, wa, n4a);
        round_tf32<<<(n4p + 255) / 256, 256>>>(W_proj, wp, n4p);
    }

    // 1) qkv = xc @ wa + b_attn  (output tf32-rounded)   [8192,3072]
    gemm_tf32<<<dim3(QKVC / 128, ROWS / 128), 256, GEMM_SMEM>>>(
        xc, wa, b_attn, qkv, ROWS, QKVC, CDIM, 1);
    // 2) attention -> y (tf32-rounded)                   [8192,1024]
    attn_tc<<<dim3(SEQ / BQ, NH, BATCH), 256, ATTN_SMEM>>>(qkv, y);
    // 3) out = y @ wp + b_proj  (full fp32 output)       [8192,1024]
    gemm_tf32<<<dim3(CDIM / 128, ROWS / 128), 256, GEMM_SMEM>>>(
        y, wp, b_proj, out, ROWS, CDIM, CDIM, 0);
}